// round 14
// baseline (speedup 1.0000x reference)
#include <cuda_runtime.h>
#include <cuda_bf16.h>
#include <math.h>
#include <stdint.h>

#define NN 50000
#define EE 800000
#define HD 96
#define FIN 32
#define EDIM 16
#define LL 3
#define BB 50

// Scratch (device globals: no allocation allowed)
__device__ float g_h[NN * HD];
__device__ float g_Pb[NN * HD];
__device__ float g_Q[NN * HD];
__device__ float g_agg[NN * HD];
__device__ float g_d2[EE];
__device__ float g_pool[BB * HD];
__device__ float g_cnt[BB];

__device__ __forceinline__ float silu_f(float x) {
    return x / (1.0f + __expf(-x));
}

__device__ __forceinline__ void red_add2(float* p, float x, float y) {
    asm volatile("red.global.add.v2.f32 [%0], {%1,%2};"
                 :: "l"(p), "f"(x), "f"(y) : "memory");
}

// ---------------------------------------------------------------------------
// legacy tensor core helpers (sm_80+ : compile OK for plain sm_103 target)
// ---------------------------------------------------------------------------
__device__ __forceinline__ void ldsm_x4(uint32_t* r, uint32_t addr) {
    asm volatile("ldmatrix.sync.aligned.m8n8.x4.shared.b16 {%0,%1,%2,%3}, [%4];"
                 : "=r"(r[0]), "=r"(r[1]), "=r"(r[2]), "=r"(r[3]) : "r"(addr));
}
__device__ __forceinline__ void ldsm_x4t(uint32_t* r, uint32_t addr) {
    asm volatile("ldmatrix.sync.aligned.m8n8.x4.trans.shared.b16 {%0,%1,%2,%3}, [%4];"
                 : "=r"(r[0]), "=r"(r[1]), "=r"(r[2]), "=r"(r[3]) : "r"(addr));
}
__device__ __forceinline__ void mma16816(float* d, const uint32_t* a,
                                         const uint32_t* b) {
    asm volatile(
        "mma.sync.aligned.m16n8k16.row.col.f32.bf16.bf16.f32 "
        "{%0,%1,%2,%3}, {%4,%5,%6,%7}, {%8,%9}, {%0,%1,%2,%3};"
        : "+f"(d[0]), "+f"(d[1]), "+f"(d[2]), "+f"(d[3])
        : "r"(a[0]), "r"(a[1]), "r"(a[2]), "r"(a[3]), "r"(b[0]), "r"(b[1]));
}

__device__ __forceinline__ void split_bf16(float v, __nv_bfloat16& hb,
                                           __nv_bfloat16& lb) {
    hb = __float2bfloat16(v);
    lb = __float2bfloat16(v - __bfloat162float(hb));
}

// ---------------------------------------------------------------------------
// encoder: h = x @ We + be
// ---------------------------------------------------------------------------
__global__ void __launch_bounds__(96) k_encoder(const float* __restrict__ x,
                                                const float* __restrict__ We,
                                                const float* __restrict__ be) {
    __shared__ float sW[FIN * HD];
    __shared__ float sb[HD];
    __shared__ float xrow[FIN];
    const int j = threadIdx.x;
    for (int i = j; i < FIN * HD; i += 96) sW[i] = We[i];
    sb[j] = be[j];
    __syncthreads();
    for (int i = blockIdx.x; i < NN; i += gridDim.x) {
        if (j < FIN) xrow[j] = x[i * FIN + j];
        __syncthreads();
        float t = sb[j];
#pragma unroll
        for (int k = 0; k < FIN; k++) t = fmaf(xrow[k], sW[k * HD + j], t);
        g_h[i * HD + j] = t;
        __syncthreads();
    }
}

__global__ void k_d2(const float* __restrict__ pos, const int* __restrict__ ei) {
    for (int e = blockIdx.x * blockDim.x + threadIdx.x; e < EE;
         e += gridDim.x * blockDim.x) {
        const int s = ei[e], d = ei[EE + e];
        const float dx = pos[s * 3 + 0] - pos[d * 3 + 0];
        const float dy = pos[s * 3 + 1] - pos[d * 3 + 1];
        const float dz = pos[s * 3 + 2] - pos[d * 3 + 2];
        g_d2[e] = dx * dx + dy * dy + dz * dz;
    }
}

__global__ void k_zero_pool() {
    const int i = blockIdx.x * blockDim.x + threadIdx.x;
    if (i < BB * HD) g_pool[i] = 0.0f;
    if (i < BB) g_cnt[i] = 0.0f;
}

// ---------------------------------------------------------------------------
// node_pre (mma): [Pb|Q] = h @ [W1a|W1b] (+b1 on Pb). Also zeroes g_agg.
// ---------------------------------------------------------------------------
#define NP_BHI 0
#define NP_BLO 38400
#define NP_AHI 76800
#define NP_ALO 103424
#define NP_B1  130048
#define NP_SMEM 130432
#define NT_NP 391

__global__ void __launch_bounds__(512) k_node_pre(const float* __restrict__ eW1l,
                                                  const float* __restrict__ eb1l) {
    extern __shared__ char smc[];
    const uint32_t sbx = (uint32_t)__cvta_generic_to_shared(smc);
    const int t = threadIdx.x;
    const int lane = t & 31;
    const int w = t >> 5;
    const int stripe = w & 7;
    const int half = w >> 3;

    for (int idx = t; idx < 96 * 192; idx += 512) {
        const int k = idx / 192;
        const int n2 = idx - k * 192;
        const int srow = k + ((n2 >= 96) ? 96 : 0);
        const int scol = (n2 >= 96) ? (n2 - 96) : n2;
        __nv_bfloat16 hb, lb;
        split_bf16(eW1l[srow * 96 + scol], hb, lb);
        const int off = k * 400 + 2 * n2;
        *reinterpret_cast<__nv_bfloat16*>(smc + NP_BHI + off) = hb;
        *reinterpret_cast<__nv_bfloat16*>(smc + NP_BLO + off) = lb;
    }
    if (t < 96) ((float*)(smc + NP_B1))[t] = eb1l[t];
    __syncthreads();
    const float* b1s = (const float*)(smc + NP_B1);

    for (int tile = blockIdx.x; tile < NT_NP; tile += gridDim.x) {
        const int base = tile * 128;
        for (int idx = t; idx < 128 * 96; idx += 512) {
            const int r = idx / 96;
            const int c = idx - r * 96;
            const int gi = base + r;
            const float v = (gi < NN) ? g_h[gi * 96 + c] : 0.0f;
            __nv_bfloat16 hb, lb;
            split_bf16(v, hb, lb);
            const int off = r * 208 + 2 * c;
            *reinterpret_cast<__nv_bfloat16*>(smc + NP_AHI + off) = hb;
            *reinterpret_cast<__nv_bfloat16*>(smc + NP_ALO + off) = lb;
        }
        {
            const float4 z4 = make_float4(0.f, 0.f, 0.f, 0.f);
            for (int idx = t; idx < 128 * 24; idx += 512) {
                const int r = idx / 24;
                const int gi = base + r;
                if (gi < NN)
                    reinterpret_cast<float4*>(g_agg)[gi * 24 + (idx - r * 24)] = z4;
            }
        }
        __syncthreads();

        uint32_t Ah[6][4], Al[6][4];
        {
            const uint32_t aoff = (uint32_t)(stripe * 16 + (lane & 15)) * 208u
                                  + (uint32_t)((lane >> 4) << 4);
#pragma unroll
            for (int kt = 0; kt < 6; kt++) {
                ldsm_x4(Ah[kt], sbx + NP_AHI + aoff + kt * 32);
                ldsm_x4(Al[kt], sbx + NP_ALO + aoff + kt * 32);
            }
        }

#pragma unroll
        for (int npl = 0; npl < 6; npl++) {
            const int np = half * 6 + npl;
            float D0[4] = {0.f, 0.f, 0.f, 0.f};
            float D1[4] = {0.f, 0.f, 0.f, 0.f};
#pragma unroll
            for (int kt = 0; kt < 6; kt++) {
                uint32_t Bh[4], Bl[4];
                const uint32_t bko = (uint32_t)(kt * 16 + (lane & 15)) * 400u
                                     + (uint32_t)(np * 32) + ((lane >> 4) << 4);
                ldsm_x4t(Bh, sbx + NP_BHI + bko);
                ldsm_x4t(Bl, sbx + NP_BLO + bko);
                mma16816(D0, Ah[kt], Bh);
                mma16816(D0, Ah[kt], Bl);
                mma16816(D0, Al[kt], Bh);
                mma16816(D1, Ah[kt], Bh + 2);
                mma16816(D1, Ah[kt], Bl + 2);
                mma16816(D1, Al[kt], Bh + 2);
            }
            const int rA = base + stripe * 16 + (lane >> 2);
            const int rB = rA + 8;
            const int q2 = 2 * (lane & 3);
            if (np < 6) {
                const int c0 = (2 * np) * 8 + q2;
                const int c1 = c0 + 8;
                if (rA < NN) {
                    *(float2*)&g_Pb[rA * 96 + c0] =
                        make_float2(D0[0] + b1s[c0], D0[1] + b1s[c0 + 1]);
                    *(float2*)&g_Pb[rA * 96 + c1] =
                        make_float2(D1[0] + b1s[c1], D1[1] + b1s[c1 + 1]);
                }
                if (rB < NN) {
                    *(float2*)&g_Pb[rB * 96 + c0] =
                        make_float2(D0[2] + b1s[c0], D0[3] + b1s[c0 + 1]);
                    *(float2*)&g_Pb[rB * 96 + c1] =
                        make_float2(D1[2] + b1s[c1], D1[3] + b1s[c1 + 1]);
                }
            } else {
                const int c0 = (2 * np) * 8 + q2 - 96;
                const int c1 = c0 + 8;
                if (rA < NN) {
                    *(float2*)&g_Q[rA * 96 + c0] = make_float2(D0[0], D0[1]);
                    *(float2*)&g_Q[rA * 96 + c1] = make_float2(D1[0], D1[1]);
                }
                if (rB < NN) {
                    *(float2*)&g_Q[rB * 96 + c0] = make_float2(D0[2], D0[3]);
                    *(float2*)&g_Q[rB * 96 + c1] = make_float2(D1[2], D1[3]);
                }
            }
        }
        __syncthreads();
    }
}

// ---------------------------------------------------------------------------
// fused edge kernel — warp-independent 16-edge stripes, no block barriers.
// mma2 + epilogue split into two n-halves to keep live regs < 128 (no spill).
// ---------------------------------------------------------------------------
#define EK_W2HI 0
#define EK_W2LO 19968
#define EK_W1CHI 39936
#define EK_W1CLO 43264
#define EK_WD 46592
#define EK_B2 46976
#define EK_UHI 47360
#define EK_ULO 73984
#define EK_EAHI 100608
#define EK_EALO 106752
#define EK_SRC 112896
#define EK_DST 113408
#define EK_D2S 113920
#define EK_SMEM 114432
#define NSTRIPE (EE / 16)

__global__ void __launch_bounds__(256, 2) k_edge(const int* __restrict__ ei,
                                                 const float* __restrict__ edge_attr,
                                                 const float* __restrict__ eW1l,
                                                 const float* __restrict__ eW2l,
                                                 const float* __restrict__ eb2l) {
    extern __shared__ char smc[];
    const uint32_t sbx = (uint32_t)__cvta_generic_to_shared(smc);
    const int t = threadIdx.x;
    const int lane = t & 31;
    const int w = t >> 5;

    // ---- one-time setup (block-wide) ----
    for (int idx = t; idx < HD * HD; idx += 256) {
        const int k = idx / HD, n = idx % HD;
        __nv_bfloat16 hb, lb;
        split_bf16(eW2l[idx], hb, lb);
        *reinterpret_cast<__nv_bfloat16*>(smc + EK_W2HI + k * 208 + 2 * n) = hb;
        *reinterpret_cast<__nv_bfloat16*>(smc + EK_W2LO + k * 208 + 2 * n) = lb;
    }
    for (int idx = t; idx < EDIM * HD; idx += 256) {
        const int k = idx / HD, n = idx % HD;
        __nv_bfloat16 hb, lb;
        split_bf16(eW1l[(193 + k) * HD + n], hb, lb);
        *reinterpret_cast<__nv_bfloat16*>(smc + EK_W1CHI + k * 208 + 2 * n) = hb;
        *reinterpret_cast<__nv_bfloat16*>(smc + EK_W1CLO + k * 208 + 2 * n) = lb;
    }
    if (t < HD) {
        ((float*)(smc + EK_WD))[t] = eW1l[192 * HD + t];
        ((float*)(smc + EK_B2))[t] = eb2l[t];
    }
    __syncthreads();

    const float* wds = (const float*)(smc + EK_WD);
    const float* b2s = (const float*)(smc + EK_B2);
    int* s_srcw = (int*)(smc + EK_SRC + w * 64);
    int* s_dstw = (int*)(smc + EK_DST + w * 64);
    float* s_d2w = (float*)(smc + EK_D2S + w * 64);
    const uint32_t u_hi = sbx + EK_UHI + w * 3328;
    const uint32_t u_lo = sbx + EK_ULO + w * 3328;
    const uint32_t ea_hi = sbx + EK_EAHI + w * 768;
    const uint32_t ea_lo = sbx + EK_EALO + w * 768;

    const int r0 = lane >> 2;
    const int r1 = r0 + 8;
    const int q2 = 2 * (lane & 3);
    const int wgid = blockIdx.x * 8 + w;
    const int wstride = gridDim.x * 8;

    for (int sp = wgid; sp < NSTRIPE; sp += wstride) {
        const int e_base = sp * 16;

        // ---- stage (warp-private) ----
        if (lane < 16) {
            s_srcw[lane] = ei[e_base + lane];
            s_dstw[lane] = ei[EE + e_base + lane];
            s_d2w[lane] = g_d2[e_base + lane];
        }
#pragma unroll
        for (int i = 0; i < 4; i++) {
            const int p = lane + 32 * i;       // 128 float2-pairs = 16 edges x 8
            const int el = p >> 3, kp = p & 7;
            const float2 v = *reinterpret_cast<const float2*>(
                edge_attr + (size_t)(e_base + el) * EDIM + 2 * kp);
            __nv_bfloat16 h0, l0, h1, l1;
            split_bf16(v.x, h0, l0);
            split_bf16(v.y, h1, l1);
            *reinterpret_cast<__nv_bfloat162*>(smc + EK_EAHI + w * 768 + el * 48 + kp * 4) =
                __nv_bfloat162(h0, h1);
            *reinterpret_cast<__nv_bfloat162*>(smc + EK_EALO + w * 768 + el * 48 + kp * 4) =
                __nv_bfloat162(l0, l1);
        }
        __syncwarp();

        // ---- mma1: D = ea @ W1c (K=16) ----
        float D[12][4];
#pragma unroll
        for (int nt = 0; nt < 12; nt++)
#pragma unroll
            for (int i = 0; i < 4; i++) D[nt][i] = 0.0f;
        {
            uint32_t Eh[4], El[4];
            const uint32_t eoff = (uint32_t)(lane & 15) * 48u + ((lane >> 4) << 4);
            ldsm_x4(Eh, ea_hi + eoff);
            ldsm_x4(El, ea_lo + eoff);
#pragma unroll
            for (int np = 0; np < 6; np++) {
                uint32_t Bh[4], Bl[4];
                const uint32_t bko = (uint32_t)(lane & 15) * 208u
                                     + (uint32_t)(np * 32) + ((lane >> 4) << 4);
                ldsm_x4t(Bh, sbx + EK_W1CHI + bko);
                ldsm_x4t(Bl, sbx + EK_W1CLO + bko);
                mma16816(D[2 * np], Eh, Bh);
                mma16816(D[2 * np], Eh, Bl);
                mma16816(D[2 * np], El, Bh);
                mma16816(D[2 * np + 1], Eh, Bh + 2);
                mma16816(D[2 * np + 1], Eh, Bl + 2);
                mma16816(D[2 * np + 1], El, Bh + 2);
            }
        }

        // ---- gather-add: D += Pb[src] + Q[dst] + wd*d2 (fragment layout) ----
        const int s0 = s_srcw[r0], d0 = s_dstw[r0];
        const int s1 = s_srcw[r1], d1 = s_dstw[r1];
        const float d2r0 = s_d2w[r0], d2r1 = s_d2w[r1];
        const float* pb0 = g_Pb + (size_t)s0 * 96;
        const float* qq0 = g_Q + (size_t)d0 * 96;
        const float* pb1 = g_Pb + (size_t)s1 * 96;
        const float* qq1 = g_Q + (size_t)d1 * 96;
#pragma unroll
        for (int nt = 0; nt < 12; nt++) {
            const int c = nt * 8 + q2;
            const float2 wv = *reinterpret_cast<const float2*>(wds + c);
            const float2 a0 = *reinterpret_cast<const float2*>(pb0 + c);
            const float2 b0 = *reinterpret_cast<const float2*>(qq0 + c);
            const float2 a1 = *reinterpret_cast<const float2*>(pb1 + c);
            const float2 b1 = *reinterpret_cast<const float2*>(qq1 + c);
            D[nt][0] += a0.x + b0.x + d2r0 * wv.x;
            D[nt][1] += a0.y + b0.y + d2r0 * wv.y;
            D[nt][2] += a1.x + b1.x + d2r1 * wv.x;
            D[nt][3] += a1.y + b1.y + d2r1 * wv.y;
        }

        // ---- u = silu(D) -> bf16 hi/lo, warp-private rows ----
#pragma unroll
        for (int nt = 0; nt < 12; nt++) {
            const int c = nt * 8 + q2;
            const float u0 = silu_f(D[nt][0]), u1 = silu_f(D[nt][1]);
            const float u2 = silu_f(D[nt][2]), u3 = silu_f(D[nt][3]);
            __nv_bfloat16 h0, l0, h1, l1;
            split_bf16(u0, h0, l0);
            split_bf16(u1, h1, l1);
            *reinterpret_cast<__nv_bfloat162*>(smc + EK_UHI + w * 3328 + r0 * 208 + 2 * c) =
                __nv_bfloat162(h0, h1);
            *reinterpret_cast<__nv_bfloat162*>(smc + EK_ULO + w * 3328 + r0 * 208 + 2 * c) =
                __nv_bfloat162(l0, l1);
            split_bf16(u2, h0, l0);
            split_bf16(u3, h1, l1);
            *reinterpret_cast<__nv_bfloat162*>(smc + EK_UHI + w * 3328 + r1 * 208 + 2 * c) =
                __nv_bfloat162(h0, h1);
            *reinterpret_cast<__nv_bfloat162*>(smc + EK_ULO + w * 3328 + r1 * 208 + 2 * c) =
                __nv_bfloat162(l0, l1);
        }
        __syncwarp();

        // ---- mma2: O = u @ W2, two n-halves with immediate epilogue ----
        uint32_t Ah[6][4], Al[6][4];
        {
            const uint32_t aoff = (uint32_t)(lane & 15) * 208u + ((lane >> 4) << 4);
#pragma unroll
            for (int kt = 0; kt < 6; kt++) {
                ldsm_x4(Ah[kt], u_hi + aoff + kt * 32);
                ldsm_x4(Al[kt], u_lo + aoff + kt * 32);
            }
        }
        float* agg0 = g_agg + (size_t)d0 * 96;
        float* agg1 = g_agg + (size_t)d1 * 96;
#pragma unroll
        for (int half = 0; half < 2; half++) {
            float O[6][4];
#pragma unroll
            for (int i = 0; i < 6; i++)
#pragma unroll
                for (int j = 0; j < 4; j++) O[i][j] = 0.0f;
#pragma unroll
            for (int kt = 0; kt < 6; kt++) {
                const uint32_t bko = (uint32_t)(kt * 16 + (lane & 15)) * 208u
                                     + ((lane >> 4) << 4) + (uint32_t)(half * 96);
#pragma unroll
                for (int npl = 0; npl < 3; npl++) {
                    uint32_t Bh[4], Bl[4];
                    ldsm_x4t(Bh, sbx + EK_W2HI + bko + npl * 32);
                    ldsm_x4t(Bl, sbx + EK_W2LO + bko + npl * 32);
                    mma16816(O[2 * npl], Ah[kt], Bh);
                    mma16816(O[2 * npl], Ah[kt], Bl);
                    mma16816(O[2 * npl], Al[kt], Bh);
                    mma16816(O[2 * npl + 1], Ah[kt], Bh + 2);
                    mma16816(O[2 * npl + 1], Ah[kt], Bl + 2);
                    mma16816(O[2 * npl + 1], Al[kt], Bh + 2);
                }
            }
            // epilogue for this half: silu(O + b2) -> red.add.v2 into g_agg
#pragma unroll
            for (int ntl = 0; ntl < 6; ntl++) {
                const int c = half * 48 + ntl * 8 + q2;
                const float2 bv = *reinterpret_cast<const float2*>(b2s + c);
                red_add2(agg0 + c, silu_f(O[ntl][0] + bv.x),
                         silu_f(O[ntl][1] + bv.y));
                red_add2(agg1 + c, silu_f(O[ntl][2] + bv.x),
                         silu_f(O[ntl][3] + bv.y));
            }
        }
    }
}

// ---------------------------------------------------------------------------
// node update (mma): h += silu([h|agg] @ nW1 + nb1) @ nW2 + nb2
// ---------------------------------------------------------------------------
#define NU_B1HI 0
#define NU_B1LO 39936
#define NU_B2HI 79872
#define NU_B2LO 99840
#define NU_AHHI 119808
#define NU_AHLO 133120
#define NU_AAHI 146432
#define NU_AALO 159744
#define NU_UHI  173056
#define NU_ULO  186368
#define NU_NB1  199680
#define NU_NB2  200064
#define NU_SMEM 200448
#define NT_NU 782

__global__ void __launch_bounds__(256) k_node_update(const float* __restrict__ nW1l,
                                                     const float* __restrict__ nb1l,
                                                     const float* __restrict__ nW2l,
                                                     const float* __restrict__ nb2l) {
    extern __shared__ char smc[];
    const uint32_t sbx = (uint32_t)__cvta_generic_to_shared(smc);
    const int t = threadIdx.x;
    const int lane = t & 31;
    const int w = t >> 5;
    const int stripe = w & 3;
    const int nh = w >> 2;

    for (int idx = t; idx < 192 * 96; idx += 256) {
        const int k = idx / 96, n = idx - (idx / 96) * 96;
        __nv_bfloat16 hb, lb;
        split_bf16(nW1l[idx], hb, lb);
        *reinterpret_cast<__nv_bfloat16*>(smc + NU_B1HI + k * 208 + 2 * n) = hb;
        *reinterpret_cast<__nv_bfloat16*>(smc + NU_B1LO + k * 208 + 2 * n) = lb;
    }
    for (int idx = t; idx < 96 * 96; idx += 256) {
        const int k = idx / 96, n = idx - (idx / 96) * 96;
        __nv_bfloat16 hb, lb;
        split_bf16(nW2l[idx], hb, lb);
        *reinterpret_cast<__nv_bfloat16*>(smc + NU_B2HI + k * 208 + 2 * n) = hb;
        *reinterpret_cast<__nv_bfloat16*>(smc + NU_B2LO + k * 208 + 2 * n) = lb;
    }
    if (t < 96) {
        ((float*)(smc + NU_NB1))[t] = nb1l[t];
        ((float*)(smc + NU_NB2))[t] = nb2l[t];
    }
    __syncthreads();
    const float* b1s = (const float*)(smc + NU_NB1);
    const float* b2s = (const float*)(smc + NU_NB2);

    for (int tile = blockIdx.x; tile < NT_NU; tile += gridDim.x) {
        const int base = tile * 64;
        for (int idx = t; idx < 64 * 96; idx += 256) {
            const int r = idx / 96;
            const int c = idx - r * 96;
            const int gi = base + r;
            const int off = r * 208 + 2 * c;
            float vh = 0.f, va = 0.f;
            if (gi < NN) {
                vh = g_h[gi * 96 + c];
                va = g_agg[gi * 96 + c];
            }
            __nv_bfloat16 hb, lb;
            split_bf16(vh, hb, lb);
            *reinterpret_cast<__nv_bfloat16*>(smc + NU_AHHI + off) = hb;
            *reinterpret_cast<__nv_bfloat16*>(smc + NU_AHLO + off) = lb;
            split_bf16(va, hb, lb);
            *reinterpret_cast<__nv_bfloat16*>(smc + NU_AAHI + off) = hb;
            *reinterpret_cast<__nv_bfloat16*>(smc + NU_AALO + off) = lb;
        }
        __syncthreads();

        const uint32_t aoff = (uint32_t)(stripe * 16 + (lane & 15)) * 208u
                              + (uint32_t)((lane >> 4) << 4);
        float D[6][4];
#pragma unroll
        for (int i = 0; i < 6; i++)
#pragma unroll
            for (int j = 0; j < 4; j++) D[i][j] = 0.0f;

        {
            uint32_t Ah[6][4], Al[6][4];
#pragma unroll
            for (int kt = 0; kt < 6; kt++) {
                ldsm_x4(Ah[kt], sbx + NU_AHHI + aoff + kt * 32);
                ldsm_x4(Al[kt], sbx + NU_AHLO + aoff + kt * 32);
            }
#pragma unroll
            for (int npl = 0; npl < 3; npl++) {
                const int np = nh * 3 + npl;
#pragma unroll
                for (int kt = 0; kt < 6; kt++) {
                    uint32_t Bh[4], Bl[4];
                    const uint32_t bko = (uint32_t)(kt * 16 + (lane & 15)) * 208u
                                         + (uint32_t)(np * 32) + ((lane >> 4) << 4);
                    ldsm_x4t(Bh, sbx + NU_B1HI + bko);
                    ldsm_x4t(Bl, sbx + NU_B1LO + bko);
                    mma16816(D[2 * npl], Ah[kt], Bh);
                    mma16816(D[2 * npl], Ah[kt], Bl);
                    mma16816(D[2 * npl], Al[kt], Bh);
                    mma16816(D[2 * npl + 1], Ah[kt], Bh + 2);
                    mma16816(D[2 * npl + 1], Ah[kt], Bl + 2);
                    mma16816(D[2 * npl + 1], Al[kt], Bh + 2);
                }
            }
        }
        {
            uint32_t Ah[6][4], Al[6][4];
#pragma unroll
            for (int kt = 0; kt < 6; kt++) {
                ldsm_x4(Ah[kt], sbx + NU_AAHI + aoff + kt * 32);
                ldsm_x4(Al[kt], sbx + NU_AALO + aoff + kt * 32);
            }
#pragma unroll
            for (int npl = 0; npl < 3; npl++) {
                const int np = nh * 3 + npl;
#pragma unroll
                for (int kt = 0; kt < 6; kt++) {
                    uint32_t Bh[4], Bl[4];
                    const uint32_t bko =
                        (uint32_t)(96 + kt * 16 + (lane & 15)) * 208u
                        + (uint32_t)(np * 32) + ((lane >> 4) << 4);
                    ldsm_x4t(Bh, sbx + NU_B1HI + bko);
                    ldsm_x4t(Bl, sbx + NU_B1LO + bko);
                    mma16816(D[2 * npl], Ah[kt], Bh);
                    mma16816(D[2 * npl], Ah[kt], Bl);
                    mma16816(D[2 * npl], Al[kt], Bh);
                    mma16816(D[2 * npl + 1], Ah[kt], Bh + 2);
                    mma16816(D[2 * npl + 1], Ah[kt], Bl + 2);
                    mma16816(D[2 * npl + 1], Al[kt], Bh + 2);
                }
            }
        }

        {
            const int g = lane >> 2, q2 = 2 * (lane & 3);
            const int r0 = stripe * 16 + g;
#pragma unroll
            for (int i = 0; i < 6; i++) {
                const int col = (nh * 6 + i) * 8 + q2;
                const float u0 = silu_f(D[i][0] + b1s[col]);
                const float u1 = silu_f(D[i][1] + b1s[col + 1]);
                const float u2 = silu_f(D[i][2] + b1s[col]);
                const float u3 = silu_f(D[i][3] + b1s[col + 1]);
                __nv_bfloat16 h0, l0, h1, l1;
                split_bf16(u0, h0, l0);
                split_bf16(u1, h1, l1);
                *reinterpret_cast<__nv_bfloat162*>(smc + NU_UHI + r0 * 208 + 2 * col) =
                    __nv_bfloat162(h0, h1);
                *reinterpret_cast<__nv_bfloat162*>(smc + NU_ULO + r0 * 208 + 2 * col) =
                    __nv_bfloat162(l0, l1);
                split_bf16(u2, h0, l0);
                split_bf16(u3, h1, l1);
                *reinterpret_cast<__nv_bfloat162*>(smc + NU_UHI + (r0 + 8) * 208 + 2 * col) =
                    __nv_bfloat162(h0, h1);
                *reinterpret_cast<__nv_bfloat162*>(smc + NU_ULO + (r0 + 8) * 208 + 2 * col) =
                    __nv_bfloat162(l0, l1);
            }
        }
        __syncthreads();

        float O[6][4];
#pragma unroll
        for (int i = 0; i < 6; i++)
#pragma unroll
            for (int j = 0; j < 4; j++) O[i][j] = 0.0f;
        {
            uint32_t Uh[6][4], Ul[6][4];
#pragma unroll
            for (int kt = 0; kt < 6; kt++) {
                ldsm_x4(Uh[kt], sbx + NU_UHI + aoff + kt * 32);
                ldsm_x4(Ul[kt], sbx + NU_ULO + aoff + kt * 32);
            }
#pragma unroll
            for (int npl = 0; npl < 3; npl++) {
                const int np = nh * 3 + npl;
#pragma unroll
                for (int kt = 0; kt < 6; kt++) {
                    uint32_t Bh[4], Bl[4];
                    const uint32_t bko = (uint32_t)(kt * 16 + (lane & 15)) * 208u
                                         + (uint32_t)(np * 32) + ((lane >> 4) << 4);
                    ldsm_x4t(Bh, sbx + NU_B2HI + bko);
                    ldsm_x4t(Bl, sbx + NU_B2LO + bko);
                    mma16816(O[2 * npl], Uh[kt], Bh);
                    mma16816(O[2 * npl], Uh[kt], Bl);
                    mma16816(O[2 * npl], Ul[kt], Bh);
                    mma16816(O[2 * npl + 1], Uh[kt], Bh + 2);
                    mma16816(O[2 * npl + 1], Uh[kt], Bl + 2);
                    mma16816(O[2 * npl + 1], Ul[kt], Bh + 2);
                }
            }
        }

        {
            const int g = lane >> 2, q2 = 2 * (lane & 3);
            const int rA = base + stripe * 16 + g;
            const int rB = rA + 8;
#pragma unroll
            for (int i = 0; i < 6; i++) {
                const int col = (nh * 6 + i) * 8 + q2;
                if (rA < NN) {
                    float2 old = *(float2*)&g_h[rA * 96 + col];
                    *(float2*)&g_h[rA * 96 + col] =
                        make_float2(old.x + O[i][0] + b2s[col],
                                    old.y + O[i][1] + b2s[col + 1]);
                }
                if (rB < NN) {
                    float2 old = *(float2*)&g_h[rB * 96 + col];
                    *(float2*)&g_h[rB * 96 + col] =
                        make_float2(old.x + O[i][2] + b2s[col],
                                    old.y + O[i][3] + b2s[col + 1]);
                }
            }
        }
        __syncthreads();
    }
}

// ---------------------------------------------------------------------------
__global__ void __launch_bounds__(96) k_pool_acc(const int* __restrict__ batch) {
    const int j = threadIdx.x;
    for (int i = blockIdx.x; i < NN; i += gridDim.x) {
        const int b = batch[i];
        atomicAdd(&g_pool[b * HD + j], g_h[i * HD + j]);
        if (j == 0) atomicAdd(&g_cnt[b], 1.0f);
    }
}

__global__ void k_final(const float* __restrict__ Wl, const float* __restrict__ bl,
                        float* __restrict__ out) {
    const int b = threadIdx.x;
    if (b >= BB) return;
    float s = 0.0f;
#pragma unroll 8
    for (int jj = 0; jj < HD; jj++) s = fmaf(g_pool[b * HD + jj], Wl[jj], s);
    out[b] = s / fmaxf(g_cnt[b], 1.0f) + bl[0];
}

// ---------------------------------------------------------------------------
extern "C" void kernel_launch(void* const* d_in, const int* in_sizes, int n_in,
                              void* d_out, int out_size) {
    const float* x = (const float*)d_in[0];
    const float* pos = (const float*)d_in[1];
    const int* ei = (const int*)d_in[2];
    const float* edge_attr = (const float*)d_in[3];
    const int* batch = (const int*)d_in[4];
    const float* We = (const float*)d_in[5];
    const float* be = (const float*)d_in[6];
    const float* eW1 = (const float*)d_in[7];
    const float* eb1 = (const float*)d_in[8];
    const float* eW2 = (const float*)d_in[9];
    const float* eb2 = (const float*)d_in[10];
    const float* nW1 = (const float*)d_in[11];
    const float* nb1 = (const float*)d_in[12];
    const float* nW2 = (const float*)d_in[13];
    const float* nb2 = (const float*)d_in[14];
    const float* Wl = (const float*)d_in[15];
    const float* bl = (const float*)d_in[16];
    float* out = (float*)d_out;

    cudaFuncSetAttribute(k_node_pre, cudaFuncAttributeMaxDynamicSharedMemorySize,
                         NP_SMEM);
    cudaFuncSetAttribute(k_edge, cudaFuncAttributeMaxDynamicSharedMemorySize,
                         EK_SMEM);
    cudaFuncSetAttribute(k_node_update,
                         cudaFuncAttributeMaxDynamicSharedMemorySize, NU_SMEM);

    k_encoder<<<888, 96>>>(x, We, be);
    k_d2<<<3125, 256>>>(pos, ei);

    for (int l = 0; l < LL; ++l) {
        const float* eW1l = eW1 + l * 209 * HD;
        const float* eb1l = eb1 + l * HD;
        const float* eW2l = eW2 + l * HD * HD;
        const float* eb2l = eb2 + l * HD;
        const float* nW1l = nW1 + l * 2 * HD * HD;
        const float* nb1l = nb1 + l * HD;
        const float* nW2l = nW2 + l * HD * HD;
        const float* nb2l = nb2 + l * HD;

        k_node_pre<<<148, 512, NP_SMEM>>>(eW1l, eb1l);   // also zeroes g_agg
        k_edge<<<296, 256, EK_SMEM>>>(ei, edge_attr, eW1l, eW2l, eb2l);
        k_node_update<<<148, 256, NU_SMEM>>>(nW1l, nb1l, nW2l, nb2l);
    }

    k_zero_pool<<<20, 256>>>();
    k_pool_acc<<<1024, 96>>>(batch);
    k_final<<<1, 64>>>(Wl, bl, out);
}

// round 16
// speedup vs baseline: 1.0604x; 1.0604x over previous
#include <cuda_runtime.h>
#include <cuda_bf16.h>
#include <math.h>
#include <stdint.h>

#define NN 50000
#define EE 800000
#define HD 96
#define FIN 32
#define EDIM 16
#define LL 3
#define BB 50

// Scratch (device globals: no allocation allowed)
__device__ float g_h[NN * HD];
__device__ float g_Pb[NN * HD];
__device__ float g_Q[NN * HD];
__device__ float g_agg[NN * HD];
__device__ float g_d2[EE];
__device__ float g_pool[BB * HD];
__device__ float g_cnt[BB];

__device__ __forceinline__ float silu_f(float x) {
    return x / (1.0f + __expf(-x));
}

__device__ __forceinline__ void red_add2(float* p, float x, float y) {
    asm volatile("red.global.add.v2.f32 [%0], {%1,%2};"
                 :: "l"(p), "f"(x), "f"(y) : "memory");
}

// ---------------------------------------------------------------------------
// legacy tensor core helpers (sm_80+ : compile OK for plain sm_103 target)
// ---------------------------------------------------------------------------
__device__ __forceinline__ void ldsm_x4(uint32_t* r, uint32_t addr) {
    asm volatile("ldmatrix.sync.aligned.m8n8.x4.shared.b16 {%0,%1,%2,%3}, [%4];"
                 : "=r"(r[0]), "=r"(r[1]), "=r"(r[2]), "=r"(r[3]) : "r"(addr));
}
__device__ __forceinline__ void ldsm_x4t(uint32_t* r, uint32_t addr) {
    asm volatile("ldmatrix.sync.aligned.m8n8.x4.trans.shared.b16 {%0,%1,%2,%3}, [%4];"
                 : "=r"(r[0]), "=r"(r[1]), "=r"(r[2]), "=r"(r[3]) : "r"(addr));
}
__device__ __forceinline__ void mma16816(float* d, const uint32_t* a,
                                         const uint32_t* b) {
    asm volatile(
        "mma.sync.aligned.m16n8k16.row.col.f32.bf16.bf16.f32 "
        "{%0,%1,%2,%3}, {%4,%5,%6,%7}, {%8,%9}, {%0,%1,%2,%3};"
        : "+f"(d[0]), "+f"(d[1]), "+f"(d[2]), "+f"(d[3])
        : "r"(a[0]), "r"(a[1]), "r"(a[2]), "r"(a[3]), "r"(b[0]), "r"(b[1]));
}

__device__ __forceinline__ void split_bf16(float v, __nv_bfloat16& hb,
                                           __nv_bfloat16& lb) {
    hb = __float2bfloat16(v);
    lb = __float2bfloat16(v - __bfloat162float(hb));
}

// pack two floats as bf16x2 hi and lo fragments
__device__ __forceinline__ void pack_hl(float x, float y, uint32_t& hi,
                                        uint32_t& lo) {
    __nv_bfloat16 hx, lx, hy, ly;
    split_bf16(x, hx, lx);
    split_bf16(y, hy, ly);
    __nv_bfloat162 H(hx, hy), L(lx, ly);
    hi = *reinterpret_cast<uint32_t*>(&H);
    lo = *reinterpret_cast<uint32_t*>(&L);
}

// silu both, then pack
__device__ __forceinline__ void pack_silu_hl(float x, float y, uint32_t& hi,
                                             uint32_t& lo) {
    pack_hl(silu_f(x), silu_f(y), hi, lo);
}

// ---------------------------------------------------------------------------
// encoder: h = x @ We + be
// ---------------------------------------------------------------------------
__global__ void __launch_bounds__(96) k_encoder(const float* __restrict__ x,
                                                const float* __restrict__ We,
                                                const float* __restrict__ be) {
    __shared__ float sW[FIN * HD];
    __shared__ float sb[HD];
    __shared__ float xrow[FIN];
    const int j = threadIdx.x;
    for (int i = j; i < FIN * HD; i += 96) sW[i] = We[i];
    sb[j] = be[j];
    __syncthreads();
    for (int i = blockIdx.x; i < NN; i += gridDim.x) {
        if (j < FIN) xrow[j] = x[i * FIN + j];
        __syncthreads();
        float t = sb[j];
#pragma unroll
        for (int k = 0; k < FIN; k++) t = fmaf(xrow[k], sW[k * HD + j], t);
        g_h[i * HD + j] = t;
        __syncthreads();
    }
}

__global__ void k_d2(const float* __restrict__ pos, const int* __restrict__ ei) {
    for (int e = blockIdx.x * blockDim.x + threadIdx.x; e < EE;
         e += gridDim.x * blockDim.x) {
        const int s = ei[e], d = ei[EE + e];
        const float dx = pos[s * 3 + 0] - pos[d * 3 + 0];
        const float dy = pos[s * 3 + 1] - pos[d * 3 + 1];
        const float dz = pos[s * 3 + 2] - pos[d * 3 + 2];
        g_d2[e] = dx * dx + dy * dy + dz * dz;
    }
}

__global__ void k_zero_pool() {
    const int i = blockIdx.x * blockDim.x + threadIdx.x;
    if (i < BB * HD) g_pool[i] = 0.0f;
    if (i < BB) g_cnt[i] = 0.0f;
}

// ---------------------------------------------------------------------------
// node_pre (mma): [Pb|Q] = h @ [W1a|W1b] (+b1 on Pb). Also zeroes g_agg.
// ---------------------------------------------------------------------------
#define NP_BHI 0
#define NP_BLO 38400
#define NP_AHI 76800
#define NP_ALO 103424
#define NP_B1  130048
#define NP_SMEM 130432
#define NT_NP 391

__global__ void __launch_bounds__(512) k_node_pre(const float* __restrict__ eW1l,
                                                  const float* __restrict__ eb1l) {
    extern __shared__ char smc[];
    const uint32_t sbx = (uint32_t)__cvta_generic_to_shared(smc);
    const int t = threadIdx.x;
    const int lane = t & 31;
    const int w = t >> 5;
    const int stripe = w & 7;
    const int half = w >> 3;

    for (int idx = t; idx < 96 * 192; idx += 512) {
        const int k = idx / 192;
        const int n2 = idx - k * 192;
        const int srow = k + ((n2 >= 96) ? 96 : 0);
        const int scol = (n2 >= 96) ? (n2 - 96) : n2;
        __nv_bfloat16 hb, lb;
        split_bf16(eW1l[srow * 96 + scol], hb, lb);
        const int off = k * 400 + 2 * n2;
        *reinterpret_cast<__nv_bfloat16*>(smc + NP_BHI + off) = hb;
        *reinterpret_cast<__nv_bfloat16*>(smc + NP_BLO + off) = lb;
    }
    if (t < 96) ((float*)(smc + NP_B1))[t] = eb1l[t];
    __syncthreads();
    const float* b1s = (const float*)(smc + NP_B1);

    for (int tile = blockIdx.x; tile < NT_NP; tile += gridDim.x) {
        const int base = tile * 128;
        for (int idx = t; idx < 128 * 96; idx += 512) {
            const int r = idx / 96;
            const int c = idx - r * 96;
            const int gi = base + r;
            const float v = (gi < NN) ? g_h[gi * 96 + c] : 0.0f;
            __nv_bfloat16 hb, lb;
            split_bf16(v, hb, lb);
            const int off = r * 208 + 2 * c;
            *reinterpret_cast<__nv_bfloat16*>(smc + NP_AHI + off) = hb;
            *reinterpret_cast<__nv_bfloat16*>(smc + NP_ALO + off) = lb;
        }
        {
            const float4 z4 = make_float4(0.f, 0.f, 0.f, 0.f);
            for (int idx = t; idx < 128 * 24; idx += 512) {
                const int r = idx / 24;
                const int gi = base + r;
                if (gi < NN)
                    reinterpret_cast<float4*>(g_agg)[gi * 24 + (idx - r * 24)] = z4;
            }
        }
        __syncthreads();

        uint32_t Ah[6][4], Al[6][4];
        {
            const uint32_t aoff = (uint32_t)(stripe * 16 + (lane & 15)) * 208u
                                  + (uint32_t)((lane >> 4) << 4);
#pragma unroll
            for (int kt = 0; kt < 6; kt++) {
                ldsm_x4(Ah[kt], sbx + NP_AHI + aoff + kt * 32);
                ldsm_x4(Al[kt], sbx + NP_ALO + aoff + kt * 32);
            }
        }

#pragma unroll
        for (int npl = 0; npl < 6; npl++) {
            const int np = half * 6 + npl;
            float D0[4] = {0.f, 0.f, 0.f, 0.f};
            float D1[4] = {0.f, 0.f, 0.f, 0.f};
#pragma unroll
            for (int kt = 0; kt < 6; kt++) {
                uint32_t Bh[4], Bl[4];
                const uint32_t bko = (uint32_t)(kt * 16 + (lane & 15)) * 400u
                                     + (uint32_t)(np * 32) + ((lane >> 4) << 4);
                ldsm_x4t(Bh, sbx + NP_BHI + bko);
                ldsm_x4t(Bl, sbx + NP_BLO + bko);
                mma16816(D0, Ah[kt], Bh);
                mma16816(D0, Ah[kt], Bl);
                mma16816(D0, Al[kt], Bh);
                mma16816(D1, Ah[kt], Bh + 2);
                mma16816(D1, Ah[kt], Bl + 2);
                mma16816(D1, Al[kt], Bh + 2);
            }
            const int rA = base + stripe * 16 + (lane >> 2);
            const int rB = rA + 8;
            const int q2 = 2 * (lane & 3);
            if (np < 6) {
                const int c0 = (2 * np) * 8 + q2;
                const int c1 = c0 + 8;
                if (rA < NN) {
                    *(float2*)&g_Pb[rA * 96 + c0] =
                        make_float2(D0[0] + b1s[c0], D0[1] + b1s[c0 + 1]);
                    *(float2*)&g_Pb[rA * 96 + c1] =
                        make_float2(D1[0] + b1s[c1], D1[1] + b1s[c1 + 1]);
                }
                if (rB < NN) {
                    *(float2*)&g_Pb[rB * 96 + c0] =
                        make_float2(D0[2] + b1s[c0], D0[3] + b1s[c0 + 1]);
                    *(float2*)&g_Pb[rB * 96 + c1] =
                        make_float2(D1[2] + b1s[c1], D1[3] + b1s[c1 + 1]);
                }
            } else {
                const int c0 = (2 * np) * 8 + q2 - 96;
                const int c1 = c0 + 8;
                if (rA < NN) {
                    *(float2*)&g_Q[rA * 96 + c0] = make_float2(D0[0], D0[1]);
                    *(float2*)&g_Q[rA * 96 + c1] = make_float2(D1[0], D1[1]);
                }
                if (rB < NN) {
                    *(float2*)&g_Q[rB * 96 + c0] = make_float2(D0[2], D0[3]);
                    *(float2*)&g_Q[rB * 96 + c1] = make_float2(D1[2], D1[3]);
                }
            }
        }
        __syncthreads();
    }
}

// ---------------------------------------------------------------------------
// fused edge kernel — warp-independent 16-edge stripes, all-register dataflow.
// Per stripe: ea A-frags direct from global; D = ea@W1c (mma);
// D += Pb[src]+Q[dst]+wd*d2 (fragment-layout gathers, wd in regs);
// u = silu(D) packed straight into A-frags (C-layout == A-layout, no smem);
// O = u@W2 per n-half with immediate silu+red.add.v2 epilogue.
// Only smem: W2 + W1c (hi/lo) + wd + b2 (one-time).
// ---------------------------------------------------------------------------
#define EK_W2HI 0
#define EK_W2LO 19968
#define EK_W1CHI 39936
#define EK_W1CLO 43264
#define EK_WD 46592
#define EK_B2 46976
#define EK_SMEM 47360
#define NSTRIPE (EE / 16)

__global__ void __launch_bounds__(256, 2) k_edge(const int* __restrict__ ei,
                                                 const float* __restrict__ edge_attr,
                                                 const float* __restrict__ eW1l,
                                                 const float* __restrict__ eW2l,
                                                 const float* __restrict__ eb2l) {
    extern __shared__ char smc[];
    const uint32_t sbx = (uint32_t)__cvta_generic_to_shared(smc);
    const int t = threadIdx.x;
    const int lane = t & 31;
    const int w = t >> 5;

    // ---- one-time setup (block-wide) ----
    for (int idx = t; idx < HD * HD; idx += 256) {
        const int k = idx / HD, n = idx % HD;
        __nv_bfloat16 hb, lb;
        split_bf16(eW2l[idx], hb, lb);
        *reinterpret_cast<__nv_bfloat16*>(smc + EK_W2HI + k * 208 + 2 * n) = hb;
        *reinterpret_cast<__nv_bfloat16*>(smc + EK_W2LO + k * 208 + 2 * n) = lb;
    }
    for (int idx = t; idx < EDIM * HD; idx += 256) {
        const int k = idx / HD, n = idx % HD;
        __nv_bfloat16 hb, lb;
        split_bf16(eW1l[(193 + k) * HD + n], hb, lb);
        *reinterpret_cast<__nv_bfloat16*>(smc + EK_W1CHI + k * 208 + 2 * n) = hb;
        *reinterpret_cast<__nv_bfloat16*>(smc + EK_W1CLO + k * 208 + 2 * n) = lb;
    }
    if (t < HD) {
        ((float*)(smc + EK_WD))[t] = eW1l[192 * HD + t];
        ((float*)(smc + EK_B2))[t] = eb2l[t];
    }
    __syncthreads();

    const float* wds = (const float*)(smc + EK_WD);
    const float* b2s = (const float*)(smc + EK_B2);

    const int r0 = lane >> 2;
    const int r1 = r0 + 8;
    const int q2 = 2 * (lane & 3);

    // loop-invariant wd fragment (cols nt*8+q2, +1)
    float2 wv[12];
#pragma unroll
    for (int nt = 0; nt < 12; nt++)
        wv[nt] = *reinterpret_cast<const float2*>(wds + nt * 8 + q2);

    const int wgid = blockIdx.x * 8 + w;
    const int wstride = gridDim.x * 8;
    const unsigned FULL = 0xffffffffu;

    for (int sp = wgid; sp < NSTRIPE; sp += wstride) {
        const int e_base = sp * 16;

        // ---- edge meta via shuffle (no smem) ----
        int sv = 0, dvv = 0;
        float d2v = 0.f;
        if (lane < 16) {
            sv = ei[e_base + lane];
            dvv = ei[EE + e_base + lane];
            d2v = g_d2[e_base + lane];
        }
        const int s0 = __shfl_sync(FULL, sv, r0);
        const int d0 = __shfl_sync(FULL, dvv, r0);
        const int s1 = __shfl_sync(FULL, sv, r1);
        const int d1 = __shfl_sync(FULL, dvv, r1);
        const float d2r0 = __shfl_sync(FULL, d2v, r0);
        const float d2r1 = __shfl_sync(FULL, d2v, r1);

        // ---- ea A-fragments direct from global (coalesced float2) ----
        uint32_t Eh[4], El[4];
        {
            const float2 v0 = *reinterpret_cast<const float2*>(
                edge_attr + (size_t)(e_base + r0) * EDIM + q2);
            const float2 v1 = *reinterpret_cast<const float2*>(
                edge_attr + (size_t)(e_base + r1) * EDIM + q2);
            const float2 v2 = *reinterpret_cast<const float2*>(
                edge_attr + (size_t)(e_base + r0) * EDIM + q2 + 8);
            const float2 v3 = *reinterpret_cast<const float2*>(
                edge_attr + (size_t)(e_base + r1) * EDIM + q2 + 8);
            pack_hl(v0.x, v0.y, Eh[0], El[0]);
            pack_hl(v1.x, v1.y, Eh[1], El[1]);
            pack_hl(v2.x, v2.y, Eh[2], El[2]);
            pack_hl(v3.x, v3.y, Eh[3], El[3]);
        }

        // ---- mma1: D = ea @ W1c (K=16) ----
        float D[12][4];
#pragma unroll
        for (int nt = 0; nt < 12; nt++)
#pragma unroll
            for (int i = 0; i < 4; i++) D[nt][i] = 0.0f;
        {
            const uint32_t bbase = (uint32_t)(lane & 15) * 208u
                                   + ((lane >> 4) << 4);
#pragma unroll
            for (int np = 0; np < 6; np++) {
                uint32_t Bh[4], Bl[4];
                ldsm_x4t(Bh, sbx + EK_W1CHI + bbase + np * 32);
                ldsm_x4t(Bl, sbx + EK_W1CLO + bbase + np * 32);
                mma16816(D[2 * np], Eh, Bh);
                mma16816(D[2 * np], Eh, Bl);
                mma16816(D[2 * np], El, Bh);
                mma16816(D[2 * np + 1], Eh, Bh + 2);
                mma16816(D[2 * np + 1], Eh, Bl + 2);
                mma16816(D[2 * np + 1], El, Bh + 2);
            }
        }

        // ---- gather-add: D += Pb[src] + Q[dst] + wd*d2 (fragment layout) ----
        const float* pb0 = g_Pb + (size_t)s0 * 96;
        const float* qq0 = g_Q + (size_t)d0 * 96;
        const float* pb1 = g_Pb + (size_t)s1 * 96;
        const float* qq1 = g_Q + (size_t)d1 * 96;
#pragma unroll
        for (int nt = 0; nt < 12; nt++) {
            const int c = nt * 8 + q2;
            const float2 a0 = *reinterpret_cast<const float2*>(pb0 + c);
            const float2 b0 = *reinterpret_cast<const float2*>(qq0 + c);
            const float2 a1 = *reinterpret_cast<const float2*>(pb1 + c);
            const float2 b1 = *reinterpret_cast<const float2*>(qq1 + c);
            D[nt][0] += a0.x + b0.x + d2r0 * wv[nt].x;
            D[nt][1] += a0.y + b0.y + d2r0 * wv[nt].y;
            D[nt][2] += a1.x + b1.x + d2r1 * wv[nt].x;
            D[nt][3] += a1.y + b1.y + d2r1 * wv[nt].y;
        }

        // ---- u = silu(D) packed straight into mma2 A-fragments ----
        // C-fragment (rows r0/r1, cols tile nt) == A-fragment tile kt=nt/2:
        //   Ah[kt][0] <- D[2kt][0..1] (r0, k=kt*16+q2)
        //   Ah[kt][1] <- D[2kt][2..3] (r1)
        //   Ah[kt][2] <- D[2kt+1][0..1] (r0, k+8)
        //   Ah[kt][3] <- D[2kt+1][2..3] (r1, k+8)
        uint32_t Ah[6][4], Al[6][4];
#pragma unroll
        for (int kt = 0; kt < 6; kt++) {
            pack_silu_hl(D[2 * kt][0], D[2 * kt][1], Ah[kt][0], Al[kt][0]);
            pack_silu_hl(D[2 * kt][2], D[2 * kt][3], Ah[kt][1], Al[kt][1]);
            pack_silu_hl(D[2 * kt + 1][0], D[2 * kt + 1][1], Ah[kt][2], Al[kt][2]);
            pack_silu_hl(D[2 * kt + 1][2], D[2 * kt + 1][3], Ah[kt][3], Al[kt][3]);
        }

        // ---- mma2: O = u @ W2, two n-halves with immediate epilogue ----
        float* agg0 = g_agg + (size_t)d0 * 96;
        float* agg1 = g_agg + (size_t)d1 * 96;
#pragma unroll
        for (int half = 0; half < 2; half++) {
            float O[6][4];
#pragma unroll
            for (int i = 0; i < 6; i++)
#pragma unroll
                for (int j = 0; j < 4; j++) O[i][j] = 0.0f;
#pragma unroll
            for (int kt = 0; kt < 6; kt++) {
                const uint32_t bko = (uint32_t)(kt * 16 + (lane & 15)) * 208u
                                     + ((lane >> 4) << 4) + (uint32_t)(half * 96);
#pragma unroll
                for (int npl = 0; npl < 3; npl++) {
                    uint32_t Bh[4], Bl[4];
                    ldsm_x4t(Bh, sbx + EK_W2HI + bko + npl * 32);
                    ldsm_x4t(Bl, sbx + EK_W2LO + bko + npl * 32);
                    mma16816(O[2 * npl], Ah[kt], Bh);
                    mma16816(O[2 * npl], Ah[kt], Bl);
                    mma16816(O[2 * npl], Al[kt], Bh);
                    mma16816(O[2 * npl + 1], Ah[kt], Bh + 2);
                    mma16816(O[2 * npl + 1], Ah[kt], Bl + 2);
                    mma16816(O[2 * npl + 1], Al[kt], Bh + 2);
                }
            }
#pragma unroll
            for (int ntl = 0; ntl < 6; ntl++) {
                const int c = half * 48 + ntl * 8 + q2;
                const float2 bv = *reinterpret_cast<const float2*>(b2s + c);
                red_add2(agg0 + c, silu_f(O[ntl][0] + bv.x),
                         silu_f(O[ntl][1] + bv.y));
                red_add2(agg1 + c, silu_f(O[ntl][2] + bv.x),
                         silu_f(O[ntl][3] + bv.y));
            }
        }
    }
}

// ---------------------------------------------------------------------------
// node update (mma): h += silu([h|agg] @ nW1 + nb1) @ nW2 + nb2
// ---------------------------------------------------------------------------
#define NU_B1HI 0
#define NU_B1LO 39936
#define NU_B2HI 79872
#define NU_B2LO 99840
#define NU_AHHI 119808
#define NU_AHLO 133120
#define NU_AAHI 146432
#define NU_AALO 159744
#define NU_UHI  173056
#define NU_ULO  186368
#define NU_NB1  199680
#define NU_NB2  200064
#define NU_SMEM 200448
#define NT_NU 782

__global__ void __launch_bounds__(256) k_node_update(const float* __restrict__ nW1l,
                                                     const float* __restrict__ nb1l,
                                                     const float* __restrict__ nW2l,
                                                     const float* __restrict__ nb2l) {
    extern __shared__ char smc[];
    const uint32_t sbx = (uint32_t)__cvta_generic_to_shared(smc);
    const int t = threadIdx.x;
    const int lane = t & 31;
    const int w = t >> 5;
    const int stripe = w & 3;
    const int nh = w >> 2;

    for (int idx = t; idx < 192 * 96; idx += 256) {
        const int k = idx / 96, n = idx - (idx / 96) * 96;
        __nv_bfloat16 hb, lb;
        split_bf16(nW1l[idx], hb, lb);
        *reinterpret_cast<__nv_bfloat16*>(smc + NU_B1HI + k * 208 + 2 * n) = hb;
        *reinterpret_cast<__nv_bfloat16*>(smc + NU_B1LO + k * 208 + 2 * n) = lb;
    }
    for (int idx = t; idx < 96 * 96; idx += 256) {
        const int k = idx / 96, n = idx - (idx / 96) * 96;
        __nv_bfloat16 hb, lb;
        split_bf16(nW2l[idx], hb, lb);
        *reinterpret_cast<__nv_bfloat16*>(smc + NU_B2HI + k * 208 + 2 * n) = hb;
        *reinterpret_cast<__nv_bfloat16*>(smc + NU_B2LO + k * 208 + 2 * n) = lb;
    }
    if (t < 96) {
        ((float*)(smc + NU_NB1))[t] = nb1l[t];
        ((float*)(smc + NU_NB2))[t] = nb2l[t];
    }
    __syncthreads();
    const float* b1s = (const float*)(smc + NU_NB1);
    const float* b2s = (const float*)(smc + NU_NB2);

    for (int tile = blockIdx.x; tile < NT_NU; tile += gridDim.x) {
        const int base = tile * 64;
        for (int idx = t; idx < 64 * 96; idx += 256) {
            const int r = idx / 96;
            const int c = idx - r * 96;
            const int gi = base + r;
            const int off = r * 208 + 2 * c;
            float vh = 0.f, va = 0.f;
            if (gi < NN) {
                vh = g_h[gi * 96 + c];
                va = g_agg[gi * 96 + c];
            }
            __nv_bfloat16 hb, lb;
            split_bf16(vh, hb, lb);
            *reinterpret_cast<__nv_bfloat16*>(smc + NU_AHHI + off) = hb;
            *reinterpret_cast<__nv_bfloat16*>(smc + NU_AHLO + off) = lb;
            split_bf16(va, hb, lb);
            *reinterpret_cast<__nv_bfloat16*>(smc + NU_AAHI + off) = hb;
            *reinterpret_cast<__nv_bfloat16*>(smc + NU_AALO + off) = lb;
        }
        __syncthreads();

        const uint32_t aoff = (uint32_t)(stripe * 16 + (lane & 15)) * 208u
                              + (uint32_t)((lane >> 4) << 4);
        float D[6][4];
#pragma unroll
        for (int i = 0; i < 6; i++)
#pragma unroll
            for (int j = 0; j < 4; j++) D[i][j] = 0.0f;

        {
            uint32_t Ah[6][4], Al[6][4];
#pragma unroll
            for (int kt = 0; kt < 6; kt++) {
                ldsm_x4(Ah[kt], sbx + NU_AHHI + aoff + kt * 32);
                ldsm_x4(Al[kt], sbx + NU_AHLO + aoff + kt * 32);
            }
#pragma unroll
            for (int npl = 0; npl < 3; npl++) {
                const int np = nh * 3 + npl;
#pragma unroll
                for (int kt = 0; kt < 6; kt++) {
                    uint32_t Bh[4], Bl[4];
                    const uint32_t bko = (uint32_t)(kt * 16 + (lane & 15)) * 208u
                                         + (uint32_t)(np * 32) + ((lane >> 4) << 4);
                    ldsm_x4t(Bh, sbx + NU_B1HI + bko);
                    ldsm_x4t(Bl, sbx + NU_B1LO + bko);
                    mma16816(D[2 * npl], Ah[kt], Bh);
                    mma16816(D[2 * npl], Ah[kt], Bl);
                    mma16816(D[2 * npl], Al[kt], Bh);
                    mma16816(D[2 * npl + 1], Ah[kt], Bh + 2);
                    mma16816(D[2 * npl + 1], Ah[kt], Bl + 2);
                    mma16816(D[2 * npl + 1], Al[kt], Bh + 2);
                }
            }
        }
        {
            uint32_t Ah[6][4], Al[6][4];
#pragma unroll
            for (int kt = 0; kt < 6; kt++) {
                ldsm_x4(Ah[kt], sbx + NU_AAHI + aoff + kt * 32);
                ldsm_x4(Al[kt], sbx + NU_AALO + aoff + kt * 32);
            }
#pragma unroll
            for (int npl = 0; npl < 3; npl++) {
                const int np = nh * 3 + npl;
#pragma unroll
                for (int kt = 0; kt < 6; kt++) {
                    uint32_t Bh[4], Bl[4];
                    const uint32_t bko =
                        (uint32_t)(96 + kt * 16 + (lane & 15)) * 208u
                        + (uint32_t)(np * 32) + ((lane >> 4) << 4);
                    ldsm_x4t(Bh, sbx + NU_B1HI + bko);
                    ldsm_x4t(Bl, sbx + NU_B1LO + bko);
                    mma16816(D[2 * npl], Ah[kt], Bh);
                    mma16816(D[2 * npl], Ah[kt], Bl);
                    mma16816(D[2 * npl], Al[kt], Bh);
                    mma16816(D[2 * npl + 1], Ah[kt], Bh + 2);
                    mma16816(D[2 * npl + 1], Ah[kt], Bl + 2);
                    mma16816(D[2 * npl + 1], Al[kt], Bh + 2);
                }
            }
        }

        {
            const int g = lane >> 2, q2 = 2 * (lane & 3);
            const int r0 = stripe * 16 + g;
#pragma unroll
            for (int i = 0; i < 6; i++) {
                const int col = (nh * 6 + i) * 8 + q2;
                const float u0 = silu_f(D[i][0] + b1s[col]);
                const float u1 = silu_f(D[i][1] + b1s[col + 1]);
                const float u2 = silu_f(D[i][2] + b1s[col]);
                const float u3 = silu_f(D[i][3] + b1s[col + 1]);
                __nv_bfloat16 h0, l0, h1, l1;
                split_bf16(u0, h0, l0);
                split_bf16(u1, h1, l1);
                *reinterpret_cast<__nv_bfloat162*>(smc + NU_UHI + r0 * 208 + 2 * col) =
                    __nv_bfloat162(h0, h1);
                *reinterpret_cast<__nv_bfloat162*>(smc + NU_ULO + r0 * 208 + 2 * col) =
                    __nv_bfloat162(l0, l1);
                split_bf16(u2, h0, l0);
                split_bf16(u3, h1, l1);
                *reinterpret_cast<__nv_bfloat162*>(smc + NU_UHI + (r0 + 8) * 208 + 2 * col) =
                    __nv_bfloat162(h0, h1);
                *reinterpret_cast<__nv_bfloat162*>(smc + NU_ULO + (r0 + 8) * 208 + 2 * col) =
                    __nv_bfloat162(l0, l1);
            }
        }
        __syncthreads();

        float O[6][4];
#pragma unroll
        for (int i = 0; i < 6; i++)
#pragma unroll
            for (int j = 0; j < 4; j++) O[i][j] = 0.0f;
        {
            uint32_t Uh[6][4], Ul[6][4];
#pragma unroll
            for (int kt = 0; kt < 6; kt++) {
                ldsm_x4(Uh[kt], sbx + NU_UHI + aoff + kt * 32);
                ldsm_x4(Ul[kt], sbx + NU_ULO + aoff + kt * 32);
            }
#pragma unroll
            for (int npl = 0; npl < 3; npl++) {
                const int np = nh * 3 + npl;
#pragma unroll
                for (int kt = 0; kt < 6; kt++) {
                    uint32_t Bh[4], Bl[4];
                    const uint32_t bko = (uint32_t)(kt * 16 + (lane & 15)) * 208u
                                         + (uint32_t)(np * 32) + ((lane >> 4) << 4);
                    ldsm_x4t(Bh, sbx + NU_B2HI + bko);
                    ldsm_x4t(Bl, sbx + NU_B2LO + bko);
                    mma16816(O[2 * npl], Uh[kt], Bh);
                    mma16816(O[2 * npl], Uh[kt], Bl);
                    mma16816(O[2 * npl], Ul[kt], Bh);
                    mma16816(O[2 * npl + 1], Uh[kt], Bh + 2);
                    mma16816(O[2 * npl + 1], Uh[kt], Bl + 2);
                    mma16816(O[2 * npl + 1], Ul[kt], Bh + 2);
                }
            }
        }

        {
            const int g = lane >> 2, q2 = 2 * (lane & 3);
            const int rA = base + stripe * 16 + g;
            const int rB = rA + 8;
#pragma unroll
            for (int i = 0; i < 6; i++) {
                const int col = (nh * 6 + i) * 8 + q2;
                if (rA < NN) {
                    float2 old = *(float2*)&g_h[rA * 96 + col];
                    *(float2*)&g_h[rA * 96 + col] =
                        make_float2(old.x + O[i][0] + b2s[col],
                                    old.y + O[i][1] + b2s[col + 1]);
                }
                if (rB < NN) {
                    float2 old = *(float2*)&g_h[rB * 96 + col];
                    *(float2*)&g_h[rB * 96 + col] =
                        make_float2(old.x + O[i][2] + b2s[col],
                                    old.y + O[i][3] + b2s[col + 1]);
                }
            }
        }
        __syncthreads();
    }
}

// ---------------------------------------------------------------------------
__global__ void __launch_bounds__(96) k_pool_acc(const int* __restrict__ batch) {
    const int j = threadIdx.x;
    for (int i = blockIdx.x; i < NN; i += gridDim.x) {
        const int b = batch[i];
        atomicAdd(&g_pool[b * HD + j], g_h[i * HD + j]);
        if (j == 0) atomicAdd(&g_cnt[b], 1.0f);
    }
}

__global__ void k_final(const float* __restrict__ Wl, const float* __restrict__ bl,
                        float* __restrict__ out) {
    const int b = threadIdx.x;
    if (b >= BB) return;
    float s = 0.0f;
#pragma unroll 8
    for (int jj = 0; jj < HD; jj++) s = fmaf(g_pool[b * HD + jj], Wl[jj], s);
    out[b] = s / fmaxf(g_cnt[b], 1.0f) + bl[0];
}

// ---------------------------------------------------------------------------
extern "C" void kernel_launch(void* const* d_in, const int* in_sizes, int n_in,
                              void* d_out, int out_size) {
    const float* x = (const float*)d_in[0];
    const float* pos = (const float*)d_in[1];
    const int* ei = (const int*)d_in[2];
    const float* edge_attr = (const float*)d_in[3];
    const int* batch = (const int*)d_in[4];
    const float* We = (const float*)d_in[5];
    const float* be = (const float*)d_in[6];
    const float* eW1 = (const float*)d_in[7];
    const float* eb1 = (const float*)d_in[8];
    const float* eW2 = (const float*)d_in[9];
    const float* eb2 = (const float*)d_in[10];
    const float* nW1 = (const float*)d_in[11];
    const float* nb1 = (const float*)d_in[12];
    const float* nW2 = (const float*)d_in[13];
    const float* nb2 = (const float*)d_in[14];
    const float* Wl = (const float*)d_in[15];
    const float* bl = (const float*)d_in[16];
    float* out = (float*)d_out;

    cudaFuncSetAttribute(k_node_pre, cudaFuncAttributeMaxDynamicSharedMemorySize,
                         NP_SMEM);
    cudaFuncSetAttribute(k_edge, cudaFuncAttributeMaxDynamicSharedMemorySize,
                         EK_SMEM);
    cudaFuncSetAttribute(k_node_update,
                         cudaFuncAttributeMaxDynamicSharedMemorySize, NU_SMEM);

    k_encoder<<<888, 96>>>(x, We, be);
    k_d2<<<3125, 256>>>(pos, ei);

    for (int l = 0; l < LL; ++l) {
        const float* eW1l = eW1 + l * 209 * HD;
        const float* eb1l = eb1 + l * HD;
        const float* eW2l = eW2 + l * HD * HD;
        const float* eb2l = eb2 + l * HD;
        const float* nW1l = nW1 + l * 2 * HD * HD;
        const float* nb1l = nb1 + l * HD;
        const float* nW2l = nW2 + l * HD * HD;
        const float* nb2l = nb2 + l * HD;

        k_node_pre<<<148, 512, NP_SMEM>>>(eW1l, eb1l);   // also zeroes g_agg
        k_edge<<<296, 256, EK_SMEM>>>(ei, edge_attr, eW1l, eW2l, eb2l);
        k_node_update<<<148, 256, NU_SMEM>>>(nW1l, nb1l, nW2l, nb2l);
    }

    k_zero_pool<<<20, 256>>>();
    k_pool_acc<<<1024, 96>>>(batch);
    k_final<<<1, 64>>>(Wl, bl, out);
}